// round 10
// baseline (speedup 1.0000x reference)
#include <cuda_runtime.h>
#include <stdint.h>

#define BB 16
#define NN 2048
#define KK 20
#define ROWS (BB * NN)
#define LSTRIDE 512          // adjacency entries per row (20 direct + transpose)
#define TCAP (LSTRIDE - KK)
#define CAP 192              // smem candidate capacity (tier-1/2 overflow -> tier-G)
#define TH1 2.2f
#define PREF1 2.19985f       // 2.2 - 1e-4 with margin
#define TH2 1.8f
#define PREF2 1.79985f

// ---- scratch (static __device__ — no allocations allowed) ----
__device__ unsigned long long g_list[(size_t)ROWS * LSTRIDE]; // (col<<32)|bits(v)
__device__ int   g_tcnt[ROWS];   // transpose counters (zero-init; writer re-zeroes)
__device__ float g_dinv[ROWS];

__device__ __forceinline__ unsigned long long u64max(unsigned long long a,
                                                     unsigned long long b) {
    return a > b ? a : b;
}

// emit winner (col, relu value v) of `row` into slot s of the adjacency lists
__device__ __forceinline__ void emit(int row, int b, int s, int col, float v) {
    unsigned long long entry =
        ((unsigned long long)col << 32) | (unsigned long long)__float_as_uint(v);
    g_list[(size_t)row * LSTRIDE + s] = entry;
    int jrow = b * NN + col;
    uint32_t t = atomicAdd((unsigned int*)&g_tcnt[jrow], 1u);
    if (t < TCAP)
        g_list[(size_t)jrow * LSTRIDE + KK + t] =
            ((unsigned long long)(row & 2047) << 32)
          | (unsigned long long)__float_as_uint(v);
}

// ---------------------------------------------------------------------------
// One block (128 threads) per row; 16 elements/thread via 4 independent
// streaming float4 loads (high MLP). Tiered threshold filter (2.2 -> 1.8)
// fetches noise only for potential candidates; exact top-K via parallel
// rank-count with jax's lowest-index tie-break (key = doped<<11 | 2047-col);
// slot = rank (ranks distinct). Tier-G safety net: register-resident 20-pass
// block-max selection over all 2048 keys (exact, ~never taken).
__global__ void __launch_bounds__(128) k_topk(const float* __restrict__ A,
                                              const float* __restrict__ Noise) {
    const int row = blockIdx.x;        // b * NN + i
    const int tid = threadIdx.x;
    const int b   = row >> 11;
    const size_t base = (size_t)row << 11;

    __shared__ unsigned long long sK[CAP];
    __shared__ float    sV[CAP];
    __shared__ uint32_t s_cnt;
    __shared__ unsigned long long s_red[4], s_win;

    if (tid == 0) s_cnt = 0;
    __syncthreads();

    const float4* a4 = (const float4*)(A + base);
    float4 v0 = __ldcs(a4 + tid);
    float4 v1 = __ldcs(a4 + 128 + tid);
    float4 v2 = __ldcs(a4 + 256 + tid);
    float4 v3 = __ldcs(a4 + 384 + tid);
    float aa[16] = {v0.x, v0.y, v0.z, v0.w, v1.x, v1.y, v1.z, v1.w,
                    v2.x, v2.y, v2.z, v2.w, v3.x, v3.y, v3.z, v3.w};
    // col of element j: (j/4)*512 + tid*4 + (j%4)

    // ---- tier 1 filter @2.2 ----
    {
        const uint32_t TH = __float_as_uint(TH1);
#pragma unroll
        for (int j = 0; j < 16; j++) {
            if (aa[j] > PREF1) {
                int col = ((j >> 2) << 9) + tid * 4 + (j & 3);
                float n = __ldcs(Noise + base + col);
                float d = __fadd_rn(aa[j], __fmul_rn(n, 1e-4f));
                uint32_t db = __float_as_uint(d);
                if (db > TH) {
                    uint32_t p = atomicAdd(&s_cnt, 1u);
                    if (p < CAP) {
                        sK[p] = ((unsigned long long)db << 11)
                              | (unsigned long long)(2047 - col);
                        sV[p] = aa[j];
                    }
                }
            }
        }
    }
    __syncthreads();
    uint32_t M = s_cnt;

    if (M < KK || M > CAP) {
        // ---- tier 2 re-filter @1.8 from registers ----
        __syncthreads();
        if (tid == 0) s_cnt = 0;
        __syncthreads();
        const uint32_t TH = __float_as_uint(TH2);
#pragma unroll
        for (int j = 0; j < 16; j++) {
            if (aa[j] > PREF2) {
                int col = ((j >> 2) << 9) + tid * 4 + (j & 3);
                float n = __ldg(Noise + base + col);
                float d = __fadd_rn(aa[j], __fmul_rn(n, 1e-4f));
                uint32_t db = __float_as_uint(d);
                if (db > TH) {
                    uint32_t p = atomicAdd(&s_cnt, 1u);
                    if (p < CAP) {
                        sK[p] = ((unsigned long long)db << 11)
                              | (unsigned long long)(2047 - col);
                        sV[p] = aa[j];
                    }
                }
            }
        }
        __syncthreads();
        M = s_cnt;
    }

    if (M >= KK && M <= CAP) {
        // ---- parallel rank-count; keys distinct -> slot = rank ----
        for (uint32_t i = tid; i < M; i += 128) {
            const unsigned long long key = sK[i];
            uint32_t rank = 0;
#pragma unroll 4
            for (uint32_t q = 0; q < M; q++)
                rank += (sK[q] > key);
            if (rank < KK)
                emit(row, b, (int)rank, 2047 - (int)(key & 2047u), sV[i]);
        }
        return;
    }

    // ---- tier G (P ~ 1e-9/row): exact 20-pass selection over all keys ----
    {
        const float4* n4 = (const float4*)(Noise + base);
        float4 w0 = __ldg(n4 + tid);
        float4 w1 = __ldg(n4 + 128 + tid);
        float4 w2 = __ldg(n4 + 256 + tid);
        float4 w3 = __ldg(n4 + 384 + tid);
        float no[16] = {w0.x, w0.y, w0.z, w0.w, w1.x, w1.y, w1.z, w1.w,
                        w2.x, w2.y, w2.z, w2.w, w3.x, w3.y, w3.z, w3.w};
        uint32_t alive = 0xFFFFu;
        for (int pass = 0; pass < KK; pass++) {
            unsigned long long m = 0;
#pragma unroll
            for (int j = 0; j < 16; j++) {
                if (alive & (1u << j)) {
                    int col = ((j >> 2) << 9) + tid * 4 + (j & 3);
                    float r = fmaxf(aa[j], 0.0f);
                    float d = __fadd_rn(r, __fmul_rn(no[j], 1e-4f));
                    unsigned long long k =
                        ((unsigned long long)__float_as_uint(d) << 11)
                      | (unsigned long long)(2047 - col);
                    m = u64max(m, k);
                }
            }
#pragma unroll
            for (int off = 16; off; off >>= 1)
                m = u64max(m, __shfl_down_sync(0xffffffffu, m, off));
            if ((tid & 31) == 0) s_red[tid >> 5] = m;
            __syncthreads();
            if (tid == 0)
                s_win = u64max(u64max(s_red[0], s_red[1]),
                               u64max(s_red[2], s_red[3]));
            __syncthreads();
            unsigned long long w = s_win;
#pragma unroll
            for (int j = 0; j < 16; j++) {
                if (alive & (1u << j)) {
                    int col = ((j >> 2) << 9) + tid * 4 + (j & 3);
                    float r = fmaxf(aa[j], 0.0f);
                    float d = __fadd_rn(r, __fmul_rn(no[j], 1e-4f));
                    unsigned long long k =
                        ((unsigned long long)__float_as_uint(d) << 11)
                      | (unsigned long long)(2047 - col);
                    if (k == w) {
                        emit(row, b, pass, col, r);
                        alive &= ~(1u << j);
                    }
                }
            }
            __syncthreads();
        }
    }
}

// ---------------------------------------------------------------------------
// Warp per row: d_i = 1 + 0.5 * sum(list values); dinv = rsqrt(d_i).
__global__ __launch_bounds__(256) void k_deg() {
    int warp = (blockIdx.x * 256 + threadIdx.x) >> 5;
    int lane = threadIdx.x & 31;
    if (warp >= ROWS) return;
    int tc = g_tcnt[warp]; if (tc > TCAP) tc = TCAP;
    int n  = KK + tc;
    float s = 0.0f;
    const unsigned long long* lst = g_list + (size_t)warp * LSTRIDE;
    for (int i = lane; i < n; i += 32)
        s += __uint_as_float((uint32_t)lst[i]);
#pragma unroll
    for (int off = 16; off; off >>= 1)
        s += __shfl_down_sync(0xffffffffu, s, off);
    if (lane == 0)
        g_dinv[warp] = rsqrtf(fmaf(0.5f, s, 1.0f));
}

// ---------------------------------------------------------------------------
// Block per row: zero smem row, scatter weighted entries + diagonal (dinv via
// L2-hot __ldg), stream dense row out evict-first; re-zero counter.
__global__ __launch_bounds__(256) void k_writer(float* __restrict__ out) {
    const int row = blockIdx.x;
    const int tid = threadIdx.x;
    const int b   = row >> 11;

    __shared__ float srow[NN];
    float4* s4 = (float4*)srow;
    s4[tid]       = make_float4(0.f, 0.f, 0.f, 0.f);
    s4[256 + tid] = make_float4(0.f, 0.f, 0.f, 0.f);

    const float di = g_dinv[row];
    int tc = g_tcnt[row]; if (tc > TCAP) tc = TCAP;
    const int n = KK + tc;
    __syncthreads();

    const unsigned long long* lst = g_list + (size_t)row * LSTRIDE;
    for (int t = tid; t < n; t += 256) {
        unsigned long long e = lst[t];
        int   col = (int)(e >> 32);
        float v   = __uint_as_float((uint32_t)e);
        float w   = 0.5f * v * di * __ldg(&g_dinv[b * NN + col]);
        atomicAdd(&srow[col], w);
    }
    if (tid == 0) atomicAdd(&srow[row & 2047], di * di);
    __syncthreads();

    float4* o4 = (float4*)(out + ((size_t)row << 11));
    __stcs(&o4[tid],       s4[tid]);
    __stcs(&o4[256 + tid], s4[256 + tid]);

    if (tid == 0) g_tcnt[row] = 0;   // next call sees zeroed counters
}

// ---------------------------------------------------------------------------
extern "C" void kernel_launch(void* const* d_in, const int* in_sizes, int n_in,
                              void* d_out, int out_size) {
    const float* A     = (const float*)d_in[0];
    const float* Noise = (const float*)d_in[1];
    float* out = (float*)d_out;

    k_topk  <<<ROWS, 128>>>(A, Noise);
    k_deg   <<<(ROWS * 32 + 255) / 256, 256>>>();
    k_writer<<<ROWS, 256>>>(out);
}

// round 11
// speedup vs baseline: 2.0841x; 2.0841x over previous
#include <cuda_runtime.h>
#include <stdint.h>

#define BB 16
#define NN 2048
#define KK 20
#define ROWS (BB * NN)
#define LSTRIDE 512          // adjacency entries per row (20 direct + transpose)
#define TCAP (LSTRIDE - KK)
#define TH1 2.2f
#define TH2 1.8f

// ---- scratch (static __device__ — no allocations allowed) ----
__device__ unsigned long long g_list[(size_t)ROWS * LSTRIDE]; // (col<<32)|bits(v)
__device__ int   g_tcnt[ROWS];   // transpose counters (zero-init; writer re-zeroes)
__device__ float g_dinv[ROWS];

// ---------------------------------------------------------------------------
// One block (256 threads) per row. Streams BOTH A and Noise as coalesced
// float4 (4 independent loads/thread, no dependent scattered fetches) and
// computes all 8 doped keys in registers. Tiered threshold filter into smem:
// 2.2 -> 1.8 -> accept-all, each tier register-only (exact, no extra loads).
// Exact top-K via parallel rank-count with jax's lowest-index tie-break
// (key = doped_bits<<11 | (2047-col)); slot = rank (ranks distinct).
__global__ __launch_bounds__(256) void k_topk(const float* __restrict__ A,
                                              const float* __restrict__ Noise) {
    const int row  = blockIdx.x;       // b * NN + i
    const int tid  = threadIdx.x;
    const int b    = row >> 11;
    const size_t base = (size_t)row << 11;

    __shared__ unsigned long long sK[NN];
    __shared__ float    sV[NN];
    __shared__ uint32_t s_cnt;
    if (tid == 0) s_cnt = 0;

    const float4* a4 = (const float4*)(A + base);
    const float4* n4 = (const float4*)(Noise + base);
    float4 av  = __ldcs(a4 + tid);
    float4 av2 = __ldcs(a4 + 256 + tid);
    float4 nv  = __ldcs(n4 + tid);
    float4 nv2 = __ldcs(n4 + 256 + tid);

    float    rv[8];
    uint32_t db[8];
    {
        float aa[8] = {av.x, av.y, av.z, av.w, av2.x, av2.y, av2.z, av2.w};
        float no[8] = {nv.x, nv.y, nv.z, nv.w, nv2.x, nv2.y, nv2.z, nv2.w};
#pragma unroll
        for (int e = 0; e < 8; e++) {
            rv[e] = fmaxf(aa[e], 0.0f);
            float d = __fadd_rn(rv[e], __fmul_rn(no[e], 1e-4f));
            db[e] = __float_as_uint(d);
        }
    }
    __syncthreads();   // covers s_cnt init

    // ---- tier 1: threshold 2.2 (register-only test) ----
    {
        const uint32_t TH = __float_as_uint(TH1);
#pragma unroll
        for (int e = 0; e < 8; e++) {
            if (db[e] > TH) {
                int col = (e < 4) ? (tid * 4 + e) : (1024 + tid * 4 + (e - 4));
                uint32_t p = atomicAdd(&s_cnt, 1u);
                sK[p] = ((unsigned long long)db[e] << 11)
                      | (unsigned long long)(2047 - col);
                sV[p] = rv[e];
            }
        }
    }
    __syncthreads();
    uint32_t M = s_cnt;

    if (M < KK) {
        // ---- tier 2: 1.8, register-only ----
        __syncthreads();
        if (tid == 0) s_cnt = 0;
        __syncthreads();
        const uint32_t TH = __float_as_uint(TH2);
#pragma unroll
        for (int e = 0; e < 8; e++) {
            if (db[e] > TH) {
                int col = (e < 4) ? (tid * 4 + e) : (1024 + tid * 4 + (e - 4));
                uint32_t p = atomicAdd(&s_cnt, 1u);
                sK[p] = ((unsigned long long)db[e] << 11)
                      | (unsigned long long)(2047 - col);
                sV[p] = rv[e];
            }
        }
        __syncthreads();
        M = s_cnt;

        if (M < KK) {
            // ---- tier 3: accept all 2048 (register-only, exact) ----
#pragma unroll
            for (int e = 0; e < 8; e++) {
                int col = (e < 4) ? (tid * 4 + e) : (1024 + tid * 4 + (e - 4));
                sK[col] = ((unsigned long long)db[e] << 11)
                        | (unsigned long long)(2047 - col);
                sV[col] = rv[e];
            }
            __syncthreads();
            M = NN;
        }
    }

    // ---- parallel rank-count; keys distinct -> slot = rank ----
    for (uint32_t i = tid; i < M; i += 256) {
        const unsigned long long key = sK[i];
        uint32_t rank = 0;
#pragma unroll 4
        for (uint32_t q = 0; q < M; q++)
            rank += (sK[q] > key);
        if (rank < KK) {
            int   col = 2047 - (int)(key & 2047u);
            float r   = sV[i];
            g_list[(size_t)row * LSTRIDE + rank] =
                ((unsigned long long)col << 32)
              | (unsigned long long)__float_as_uint(r);
            int jrow = b * NN + col;                          // transpose entry
            uint32_t t = atomicAdd((unsigned int*)&g_tcnt[jrow], 1u);
            if (t < TCAP)
                g_list[(size_t)jrow * LSTRIDE + KK + t] =
                    ((unsigned long long)(row & 2047) << 32)
                  | (unsigned long long)__float_as_uint(r);
        }
    }
}

// ---------------------------------------------------------------------------
// Warp per row: d_i = 1 + 0.5 * sum(list values); dinv = rsqrt(d_i).
__global__ __launch_bounds__(256) void k_deg() {
    int warp = (blockIdx.x * 256 + threadIdx.x) >> 5;
    int lane = threadIdx.x & 31;
    if (warp >= ROWS) return;
    int tc = g_tcnt[warp]; if (tc > TCAP) tc = TCAP;
    int n  = KK + tc;
    float s = 0.0f;
    const unsigned long long* lst = g_list + (size_t)warp * LSTRIDE;
    for (int i = lane; i < n; i += 32)
        s += __uint_as_float((uint32_t)lst[i]);
#pragma unroll
    for (int off = 16; off; off >>= 1)
        s += __shfl_down_sync(0xffffffffu, s, off);
    if (lane == 0)
        g_dinv[warp] = rsqrtf(fmaf(0.5f, s, 1.0f));
}

// ---------------------------------------------------------------------------
// Block per row: zero smem row, scatter weighted entries + diagonal (dinv via
// L2-hot __ldg), stream dense row out evict-first; re-zero counter.
__global__ __launch_bounds__(256) void k_writer(float* __restrict__ out) {
    const int row = blockIdx.x;
    const int tid = threadIdx.x;
    const int b   = row >> 11;

    __shared__ float srow[NN];
    float4* s4 = (float4*)srow;
    s4[tid]       = make_float4(0.f, 0.f, 0.f, 0.f);
    s4[256 + tid] = make_float4(0.f, 0.f, 0.f, 0.f);

    const float di = g_dinv[row];
    int tc = g_tcnt[row]; if (tc > TCAP) tc = TCAP;
    const int n = KK + tc;
    __syncthreads();

    const unsigned long long* lst = g_list + (size_t)row * LSTRIDE;
    for (int t = tid; t < n; t += 256) {
        unsigned long long e = lst[t];
        int   col = (int)(e >> 32);
        float v   = __uint_as_float((uint32_t)e);
        float w   = 0.5f * v * di * __ldg(&g_dinv[b * NN + col]);
        atomicAdd(&srow[col], w);
    }
    if (tid == 0) atomicAdd(&srow[row & 2047], di * di);
    __syncthreads();

    float4* o4 = (float4*)(out + ((size_t)row << 11));
    __stcs(&o4[tid],       s4[tid]);
    __stcs(&o4[256 + tid], s4[256 + tid]);

    if (tid == 0) g_tcnt[row] = 0;   // next call sees zeroed counters
}

// ---------------------------------------------------------------------------
extern "C" void kernel_launch(void* const* d_in, const int* in_sizes, int n_in,
                              void* d_out, int out_size) {
    const float* A     = (const float*)d_in[0];
    const float* Noise = (const float*)d_in[1];
    float* out = (float*)d_out;

    k_topk  <<<ROWS, 256>>>(A, Noise);
    k_deg   <<<(ROWS * 32 + 255) / 256, 256>>>();
    k_writer<<<ROWS, 256>>>(out);
}